// round 6
// baseline (speedup 1.0000x reference)
#include <cuda_runtime.h>
#include <math.h>

// ---------------------------------------------------------------------------
// Problem constants
// ---------------------------------------------------------------------------
namespace {
constexpr int B_   = 8;
constexpr int S_   = 512;
constexpr int D_   = 1024;
constexpr int H_   = 8;
constexpr int DP_  = 128;              // head dim
constexpr int BH_  = B_ * H_;          // 64
constexpr int MS_  = B_ * S_;          // 4096  (rows of x)
constexpr int NR_  = 96 * S_;          // 49152 RNN rows
constexpr int ROWS_ = BH_ * S_;        // 32768 (b,h,q) rows
constexpr int NOUT_ = MS_ * D_;        // 4194304 elements of `out`
constexpr float INV_SCALE = 0.08838834764831845f;  // 1/sqrt(128)
constexpr int ASW = 264;               // A smem row stride (words), 264%32==8
constexpr int BSW = 136;               // B smem row stride (words), 136%32==8
constexpr int SMEMB = (2 * 16 * ASW + 2 * 16 * BSW) * 4;  // 51200 bytes
}

// ---------------------------------------------------------------------------
// Scratch (static device globals -- no runtime allocation allowed)
// ---------------------------------------------------------------------------
__device__ float g_q  [BH_ * S_ * DP_];
__device__ float g_k  [BH_ * S_ * DP_];
__device__ float g_v  [BH_ * S_ * DP_];
__device__ float g_ctx[BH_ * S_ * DP_];
__device__ float g_A  [NR_ * DP_];
__device__ float g_Bm [NR_ * DP_];
__device__ float g_H1f[NR_ * DP_];
__device__ float g_H1b[NR_ * DP_];
__device__ float g_Yf [NR_ * DP_];
__device__ float g_P  [ROWS_ * 65];
__device__ float g_R  [ROWS_ * 65];
__device__ int   g_mask[MS_];
__device__ float g_attn_fb[(size_t)BH_ * S_ * S_];

// ---------------------------------------------------------------------------
// tf32 helpers
// ---------------------------------------------------------------------------
__device__ __forceinline__ unsigned f2tf(float x) {
    unsigned r;
    asm("cvt.rna.tf32.f32 %0, %1;" : "=r"(r) : "f"(x));
    return r;
}

__device__ __forceinline__ void mma_tf32(float* d, const unsigned* a, const unsigned* b) {
    asm volatile(
        "mma.sync.aligned.m16n8k8.row.col.f32.tf32.tf32.f32 "
        "{%0,%1,%2,%3}, {%4,%5,%6,%7}, {%8,%9}, {%0,%1,%2,%3};\n"
        : "+f"(d[0]), "+f"(d[1]), "+f"(d[2]), "+f"(d[3])
        : "r"(a[0]), "r"(a[1]), "r"(a[2]), "r"(a[3]), "r"(b[0]), "r"(b[1]));
}

// ---------------------------------------------------------------------------
// 256x128 tf32-MMA GEMM cores. 256 threads = 8 warps (4M x 2N),
// warp tile 64x64. Smem k-major, strides 264/136 (conflict-free fragments).
//   mm256_tn:  C = A * B^T   (A: [M,K] rm, B: [N,K] rm)
//   mm256_nn:  C = A * B     (A: [M,K] rm, B: [K,N] rm)
// ---------------------------------------------------------------------------
#define MM_COMPUTE(bO)                                                        \
    _Pragma("unroll")                                                         \
    for (int kc = 0; kc < 16; kc += 8) {                                      \
        unsigned af[4][4], bf[8][2];                                          \
        _Pragma("unroll")                                                     \
        for (int mi = 0; mi < 4; mi++) {                                      \
            int m0 = wm + 16 * mi;                                            \
            af[mi][0] = As[(bO) + kc + la3][m0 + lg];                         \
            af[mi][1] = As[(bO) + kc + la3][m0 + 8 + lg];                     \
            af[mi][2] = As[(bO) + kc + 4 + la3][m0 + lg];                     \
            af[mi][3] = As[(bO) + kc + 4 + la3][m0 + 8 + lg];                 \
        }                                                                     \
        _Pragma("unroll")                                                     \
        for (int nj = 0; nj < 8; nj++) {                                      \
            int n0 = wn + 8 * nj;                                             \
            bf[nj][0] = Bs[(bO) + kc + la3][n0 + lg];                         \
            bf[nj][1] = Bs[(bO) + kc + 4 + la3][n0 + lg];                     \
        }                                                                     \
        _Pragma("unroll")                                                     \
        for (int mi = 0; mi < 4; mi++)                                        \
            _Pragma("unroll")                                                 \
            for (int nj = 0; nj < 8; nj++)                                    \
                mma_tf32(acc[mi][nj], af[mi], bf[nj]);                        \
    }

#define MM_STORE_A(bO)                                                        \
    As[(bO)+0][ar]=f2tf(a0.x);  As[(bO)+1][ar]=f2tf(a0.y);                    \
    As[(bO)+2][ar]=f2tf(a0.z);  As[(bO)+3][ar]=f2tf(a0.w);                    \
    As[(bO)+4][ar]=f2tf(a1.x);  As[(bO)+5][ar]=f2tf(a1.y);                    \
    As[(bO)+6][ar]=f2tf(a1.z);  As[(bO)+7][ar]=f2tf(a1.w);                    \
    As[(bO)+8][ar]=f2tf(a2.x);  As[(bO)+9][ar]=f2tf(a2.y);                    \
    As[(bO)+10][ar]=f2tf(a2.z); As[(bO)+11][ar]=f2tf(a2.w);                   \
    As[(bO)+12][ar]=f2tf(a3.x); As[(bO)+13][ar]=f2tf(a3.y);                   \
    As[(bO)+14][ar]=f2tf(a3.z); As[(bO)+15][ar]=f2tf(a3.w);

#define MM_EPILOGUE                                                           \
    _Pragma("unroll")                                                         \
    for (int mi = 0; mi < 4; mi++)                                            \
        _Pragma("unroll")                                                     \
        for (int nj = 0; nj < 8; nj++) {                                      \
            int r0 = wm + 16 * mi + lg, c0 = wn + 8 * nj + 2 * la3;           \
            storeC(r0,     c0,     acc[mi][nj][0]);                           \
            storeC(r0,     c0 + 1, acc[mi][nj][1]);                           \
            storeC(r0 + 8, c0,     acc[mi][nj][2]);                           \
            storeC(r0 + 8, c0 + 1, acc[mi][nj][3]);                           \
        }

template <class FA, class FB, class FC>
__device__ __forceinline__ void mm256_tn(int K, FA loadA, FB loadB, FC storeC) {
    extern __shared__ unsigned sm_[];
    unsigned (*As)[ASW] = (unsigned(*)[ASW])sm_;
    unsigned (*Bs)[BSW] = (unsigned(*)[BSW])(sm_ + 2 * 16 * ASW);
    float acc[4][8][4] = {};
    const int tid  = threadIdx.x;
    const int lane = tid & 31;
    const int warp = tid >> 5;
    const int la3  = lane & 3, lg = lane >> 2;
    const int wm   = (warp & 3) * 64, wn = (warp >> 2) * 64;
    const int ar   = tid;                // A stage row 0..255
    const int br   = tid >> 1;           // B stage row 0..127
    const int bko  = (tid & 1) * 8;      // B k offset 0/8

    float4 a0 = loadA(ar, 0), a1 = loadA(ar, 4), a2 = loadA(ar, 8), a3 = loadA(ar, 12);
    float4 b0 = loadB(br, bko), b1 = loadB(br, bko + 4);
    MM_STORE_A(0)
    Bs[bko+0][br]=f2tf(b0.x); Bs[bko+1][br]=f2tf(b0.y);
    Bs[bko+2][br]=f2tf(b0.z); Bs[bko+3][br]=f2tf(b0.w);
    Bs[bko+4][br]=f2tf(b1.x); Bs[bko+5][br]=f2tf(b1.y);
    Bs[bko+6][br]=f2tf(b1.z); Bs[bko+7][br]=f2tf(b1.w);
    __syncthreads();
    int bO = 0;
    for (int k0 = 16; k0 <= K; k0 += 16) {
        const bool more = (k0 < K);
        if (more) {
            a0 = loadA(ar, k0); a1 = loadA(ar, k0 + 4);
            a2 = loadA(ar, k0 + 8); a3 = loadA(ar, k0 + 12);
            b0 = loadB(br, k0 + bko); b1 = loadB(br, k0 + bko + 4);
        }
        MM_COMPUTE(bO)
        if (more) {
            int nO = bO ^ 16;
            MM_STORE_A(nO)
            Bs[nO+bko+0][br]=f2tf(b0.x); Bs[nO+bko+1][br]=f2tf(b0.y);
            Bs[nO+bko+2][br]=f2tf(b0.z); Bs[nO+bko+3][br]=f2tf(b0.w);
            Bs[nO+bko+4][br]=f2tf(b1.x); Bs[nO+bko+5][br]=f2tf(b1.y);
            Bs[nO+bko+6][br]=f2tf(b1.z); Bs[nO+bko+7][br]=f2tf(b1.w);
            __syncthreads();
            bO = nO;
        }
    }
    MM_EPILOGUE
}

template <class FA, class FB, class FC>
__device__ __forceinline__ void mm256_nn(int K, FA loadA, FB loadB, FC storeC) {
    extern __shared__ unsigned sm_[];
    unsigned (*As)[ASW] = (unsigned(*)[ASW])sm_;
    unsigned (*Bs)[BSW] = (unsigned(*)[BSW])(sm_ + 2 * 16 * ASW);
    float acc[4][8][4] = {};
    const int tid  = threadIdx.x;
    const int lane = tid & 31;
    const int warp = tid >> 5;
    const int la3  = lane & 3, lg = lane >> 2;
    const int wm   = (warp & 3) * 64, wn = (warp >> 2) * 64;
    const int ar   = tid;                // A stage row
    const int bk   = tid >> 4;           // B k row 0..15
    const int bn2  = (tid & 15) * 8;     // B col 0..120

    float4 a0 = loadA(ar, 0), a1 = loadA(ar, 4), a2 = loadA(ar, 8), a3 = loadA(ar, 12);
    float4 b0 = loadB(bk, bn2), b1 = loadB(bk, bn2 + 4);
    MM_STORE_A(0)
    Bs[bk][bn2+0]=f2tf(b0.x); Bs[bk][bn2+1]=f2tf(b0.y);
    Bs[bk][bn2+2]=f2tf(b0.z); Bs[bk][bn2+3]=f2tf(b0.w);
    Bs[bk][bn2+4]=f2tf(b1.x); Bs[bk][bn2+5]=f2tf(b1.y);
    Bs[bk][bn2+6]=f2tf(b1.z); Bs[bk][bn2+7]=f2tf(b1.w);
    __syncthreads();
    int bO = 0;
    for (int k0 = 16; k0 <= K; k0 += 16) {
        const bool more = (k0 < K);
        if (more) {
            a0 = loadA(ar, k0); a1 = loadA(ar, k0 + 4);
            a2 = loadA(ar, k0 + 8); a3 = loadA(ar, k0 + 12);
            b0 = loadB(k0 + bk, bn2); b1 = loadB(k0 + bk, bn2 + 4);
        }
        MM_COMPUTE(bO)
        if (more) {
            int nO = bO ^ 16;
            MM_STORE_A(nO)
            Bs[nO+bk][bn2+0]=f2tf(b0.x); Bs[nO+bk][bn2+1]=f2tf(b0.y);
            Bs[nO+bk][bn2+2]=f2tf(b0.z); Bs[nO+bk][bn2+3]=f2tf(b0.w);
            Bs[nO+bk][bn2+4]=f2tf(b1.x); Bs[nO+bk][bn2+5]=f2tf(b1.y);
            Bs[nO+bk][bn2+6]=f2tf(b1.z); Bs[nO+bk][bn2+7]=f2tf(b1.w);
            __syncthreads();
            bO = nO;
        }
    }
    MM_EPILOGUE
}

// ---------------------------------------------------------------------------
// 0) Mask normalization (detect uint8 / int32 / float32 encodings)
// ---------------------------------------------------------------------------
__global__ void mask_norm_kernel(const void* raw) {
    __shared__ int f_int, f_flt;
    const unsigned int* w = (const unsigned int*)raw;
    int t = threadIdx.x;  // 1024 threads
    if (t == 0) { f_int = 1; f_flt = 1; }
    __syncthreads();
    unsigned int x = w[t];
    if (x != 0u && x != 1u) f_int = 0;
    if (x != 0u && x != 0x3F800000u) f_flt = 0;
    __syncthreads();
    if (f_int) {
        for (int i = t; i < MS_; i += 1024) g_mask[i] = (int)w[i];
    } else if (f_flt) {
        const float* f = (const float*)raw;
        for (int i = t; i < MS_; i += 1024) g_mask[i] = (f[i] != 0.f);
    } else {
        const unsigned char* bts = (const unsigned char*)raw;
        for (int i = t; i < MS_; i += 1024) g_mask[i] = (bts[i] != 0);
    }
}

// ---------------------------------------------------------------------------
// 1) QKV projections (MMA) + bias + mask-zero + head-major scatter
// ---------------------------------------------------------------------------
__global__ void __launch_bounds__(256, 1) qkv_kernel(
    const float* __restrict__ x,
    const float* __restrict__ Wq, const float* __restrict__ bq,
    const float* __restrict__ Wk, const float* __restrict__ bk,
    const float* __restrict__ Wv, const float* __restrict__ bv) {
    const int z = blockIdx.z;
    const float* W    = (z == 0) ? Wq : (z == 1) ? Wk : Wv;
    const float* bias = (z == 0) ? bq : (z == 1) ? bk : bv;
    float* out        = (z == 0) ? g_q : (z == 1) ? g_k : g_v;
    const int bm = blockIdx.y * 256, bn = blockIdx.x * 128;
    mm256_tn(D_,
        [&](int r, int k) { return *(const float4*)(x + (size_t)(bm + r) * D_ + k); },
        [&](int r, int k) { return *(const float4*)(W + (size_t)(bn + r) * D_ + k); },
        [&](int il, int jl, float v) {
            int m = bm + il, n = bn + jl;
            int b = m >> 9, s = m & 511;
            int h = n >> 7, d = n & 127;
            float val = g_mask[m] ? 0.f : (v + bias[n]);
            out[((size_t)((b * H_ + h) * S_ + s)) * DP_ + d] = val;
        });
}

// ---------------------------------------------------------------------------
// 2) RNN input GEMMs
// ---------------------------------------------------------------------------
__device__ __forceinline__ const float* feats_row(int rr) {
    int f = rr >> 14;
    int rem = rr & 16383;
    int bh4 = rem >> 9;
    int s   = rem & 511;
    int b = bh4 >> 2, hh = bh4 & 3;
    const float* src = (f == 0) ? g_q : (f == 1) ? g_k : g_v;
    return src + ((size_t)((b * H_ + 4 + hh) * S_ + s)) * DP_;
}

__global__ void __launch_bounds__(256, 1) rnn_in_kernel(
    const float* __restrict__ Wih_f, const float* __restrict__ bih_f,
    const float* __restrict__ Wih_b, const float* __restrict__ bih_b) {
    const int z = blockIdx.z;
    const float* W    = z ? Wih_b : Wih_f;
    const float* bias = z ? bih_b : bih_f;
    float* dst        = z ? g_Bm : g_A;
    const int bm = blockIdx.y * 256;
    mm256_tn(DP_,
        [&](int r, int k) { return *(const float4*)(feats_row(bm + r) + k); },
        [&](int r, int k) { return *(const float4*)(W + (size_t)r * DP_ + k); },
        [&](int il, int jl, float v) {
            dst[(size_t)(bm + il) * DP_ + jl] = v + bias[jl];
        });
}

// ---------------------------------------------------------------------------
// 3) First RNN step (elementwise)
// ---------------------------------------------------------------------------
__global__ void rnn_h1_kernel(const float* __restrict__ bih_f,
                              const float* __restrict__ bhh_f,
                              const float* __restrict__ bhh_b) {
    int gid = blockIdx.x * blockDim.x + threadIdx.x;
    if (gid >= NR_ * DP_) return;
    int r = gid >> 7, d = gid & 127;
    int s = r & 511;
    float af = s ? g_A[gid - DP_] : bih_f[d];
    g_H1f[gid] = tanhf(af + bhh_f[d]);
    g_H1b[gid] = tanhf(g_Bm[gid] + bhh_b[d]);
}

// ---------------------------------------------------------------------------
// 4) Forward step 2:  Yf = tanh( A + H1f@Whh_f^T + bhh_f )
// ---------------------------------------------------------------------------
__global__ void __launch_bounds__(256, 1) rnn_h2f_kernel(
    const float* __restrict__ Whh_f, const float* __restrict__ bhh_f) {
    const int bm = blockIdx.y * 256;
    mm256_tn(DP_,
        [&](int r, int k) { return *(const float4*)(g_H1f + (size_t)(bm + r) * DP_ + k); },
        [&](int r, int k) { return *(const float4*)(Whh_f + (size_t)r * DP_ + k); },
        [&](int il, int jl, float v) {
            size_t idx = (size_t)(bm + il) * DP_ + jl;
            g_Yf[idx] = tanhf(v + g_A[idx] + bhh_f[jl]);
        });
}

// ---------------------------------------------------------------------------
// 5) Backward step 2 + combine + scatter back into q/k/v heads 4..7
// ---------------------------------------------------------------------------
__global__ void __launch_bounds__(256, 1) rnn_h2b_kernel(
    const float* __restrict__ Whh_b, const float* __restrict__ bih_b,
    const float* __restrict__ bhh_b) {
    const int bm = blockIdx.y * 256;
    mm256_tn(DP_,
        [&](int r, int k) { return *(const float4*)(g_H1b + (size_t)(bm + r) * DP_ + k); },
        [&](int r, int k) { return *(const float4*)(Whh_b + (size_t)r * DP_ + k); },
        [&](int il, int jl, float v) {
            int m = bm + il, n = jl;
            int s = m & 511;
            float shiftB = s ? g_Bm[(size_t)(m - 1) * DP_ + n] : bih_b[n];
            float y = g_Yf[(size_t)m * DP_ + n] + tanhf(v + shiftB + bhh_b[n]);
            int f = m >> 14, rem = m & 16383, bh4 = rem >> 9;
            int b = bh4 >> 2, hh = bh4 & 3;
            float* dst = (f == 0) ? g_q : (f == 1) ? g_k : g_v;
            dst[((size_t)((b * H_ + 4 + hh) * S_ + s)) * DP_ + n] = y;
        });
}

// ---------------------------------------------------------------------------
// 6) P[row,j] = (q[row] . rel_emb[j]) / SCALE
// ---------------------------------------------------------------------------
__global__ void p_kernel(const float* __restrict__ rel_emb) {
    int gid = blockIdx.x * blockDim.x + threadIdx.x;
    if (gid >= ROWS_ * 65) return;
    int row = gid / 65, j = gid - row * 65;
    const float* qr = g_q + (size_t)row * DP_;
    const float* er = rel_emb + (size_t)j * DP_;
    float s = 0.f;
#pragma unroll 8
    for (int d = 0; d < DP_; d++) s = fmaf(qr[d], er[d], s);
    g_P[gid] = s * INV_SCALE;
}

// ---------------------------------------------------------------------------
// 7) scores (pre-softmax) into the attn buffer
// ---------------------------------------------------------------------------
__global__ void __launch_bounds__(256, 1) scores_kernel(float* __restrict__ attn,
                                                        int attn_in_out) {
    float* ap = attn_in_out ? attn : g_attn_fb;
    const int z = blockIdx.z;
    const int b = z >> 3;
    const int bm = blockIdx.y * 256, bn = blockIdx.x * 128;
    const float* qb = g_q + (size_t)z * S_ * DP_;
    const float* kb = g_k + (size_t)z * S_ * DP_;
    mm256_tn(DP_,
        [&](int r, int k) { return *(const float4*)(qb + (size_t)(bm + r) * DP_ + k); },
        [&](int r, int k) { return *(const float4*)(kb + (size_t)(bn + r) * DP_ + k); },
        [&](int il, int jl, float v) {
            int qi = bm + il, ki = bn + jl;
            float val;
            if (g_mask[b * S_ + ki]) {
                val = -1e18f;
            } else {
                int off = ki - qi;
                off = off < -32 ? -32 : (off > 32 ? 32 : off);
                val = v * INV_SCALE + g_P[((size_t)z * S_ + qi) * 65 + off + 32];
            }
            ap[(size_t)z * S_ * S_ + (size_t)qi * S_ + ki] = val;
        });
}

// ---------------------------------------------------------------------------
// 8) Softmax per row + bucketed rel sums R
// ---------------------------------------------------------------------------
__device__ __forceinline__ float blk_reduce(float v, float* red, bool is_max) {
#pragma unroll
    for (int o = 16; o > 0; o >>= 1) {
        float w = __shfl_xor_sync(0xffffffffu, v, o);
        v = is_max ? fmaxf(v, w) : (v + w);
    }
    int warp = threadIdx.x >> 5, lane = threadIdx.x & 31;
    if (lane == 0) red[warp] = v;
    __syncthreads();
    float r = red[0];
#pragma unroll
    for (int i = 1; i < 8; i++) r = is_max ? fmaxf(r, red[i]) : (r + red[i]);
    __syncthreads();
    return r;
}

__global__ void __launch_bounds__(256) softmax_kernel(float* __restrict__ attn,
                                                      int attn_in_out) {
    float* ap = attn_in_out ? attn : g_attn_fb;
    int row = blockIdx.x;
    int q = row & 511;
    float* p = ap + (size_t)row * S_;
    __shared__ float sh[S_];
    __shared__ float red[8];
    int t = threadIdx.x;
    float v0 = p[t], v1 = p[t + 256];
    float mx = blk_reduce(fmaxf(v0, v1), red, true);
    float e0 = expf(v0 - mx), e1 = expf(v1 - mx);
    float sum = blk_reduce(e0 + e1, red, false);
    float inv = 1.f / sum;
    e0 *= inv; e1 *= inv;
    p[t] = e0; p[t + 256] = e1;
    sh[t] = e0; sh[t + 256] = e1;
    float r0 = 0.f, r64 = 0.f;
    if (t <= q - 32)        r0  += e0;
    if (t >= q + 32)        r64 += e0;
    if (t + 256 <= q - 32)  r0  += e1;
    if (t + 256 >= q + 32)  r64 += e1;
    r0  = blk_reduce(r0,  red, false);
    r64 = blk_reduce(r64, red, false);
    float* Rr = g_R + (size_t)row * 65;
    if (t == 0) { Rr[0] = r0; Rr[64] = r64; }
    if (t >= 1 && t <= 63) {
        int k = q + t - 32;
        Rr[t] = (k >= 0 && k < S_) ? sh[k] : 0.f;
    }
}

// ---------------------------------------------------------------------------
// 9) ctx = attn @ v  (NN MMA, per bh)
// ---------------------------------------------------------------------------
__global__ void __launch_bounds__(256, 1) ctx_kernel(const float* __restrict__ attn,
                                                     int attn_in_out) {
    const float* ap = attn_in_out ? attn : g_attn_fb;
    const int z = blockIdx.z;
    const int bm = blockIdx.y * 256;
    const float* Ab = ap + (size_t)z * S_ * S_;
    const float* Vb = g_v + (size_t)z * S_ * DP_;
    mm256_nn(S_,
        [&](int r, int k) { return *(const float4*)(Ab + (size_t)(bm + r) * S_ + k); },
        [&](int k, int n) { return *(const float4*)(Vb + (size_t)k * DP_ + n); },
        [&](int il, int jl, float v) {
            g_ctx[(size_t)z * S_ * DP_ + (size_t)(bm + il) * DP_ + jl] = v;
        });
}

// ---------------------------------------------------------------------------
// 10) ctx += R @ rel_emb
// ---------------------------------------------------------------------------
__global__ void ctx_rel_kernel(const float* __restrict__ rel_emb) {
    int gid = blockIdx.x * blockDim.x + threadIdx.x;
    if (gid >= ROWS_ * DP_) return;
    int row = gid >> 7, d = gid & 127;
    const float* Rr = g_R + (size_t)row * 65;
    float s = 0.f;
#pragma unroll
    for (int j = 0; j < 65; j++) s = fmaf(Rr[j], rel_emb[(size_t)j * DP_ + d], s);
    g_ctx[gid] += s;
}

// ---------------------------------------------------------------------------
// 11) out = ctx_perm @ Wo^T + bo
// ---------------------------------------------------------------------------
__global__ void __launch_bounds__(256, 1) out_kernel(const float* __restrict__ Wo,
                                                     const float* __restrict__ bo,
                                                     float* __restrict__ out) {
    const int bm = blockIdx.y * 256, bn = blockIdx.x * 128;
    mm256_tn(D_,
        [&](int r, int k) {
            int m = bm + r;
            int b = m >> 9, s = m & 511;
            int h = k >> 7, d = k & 127;
            return *(const float4*)(g_ctx + ((size_t)((b * H_ + h) * S_ + s)) * DP_ + d);
        },
        [&](int r, int k) { return *(const float4*)(Wo + (size_t)(bn + r) * D_ + k); },
        [&](int il, int jl, float v) {
            int m = bm + il, n = bn + jl;
            out[(size_t)m * D_ + n] = v + bo[n];
        });
}

// ---------------------------------------------------------------------------
// Host launcher
// ---------------------------------------------------------------------------
extern "C" void kernel_launch(void* const* d_in, const int* in_sizes, int n_in,
                              void* d_out, int out_size) {
    const float* x     = (const float*)d_in[0];
    const void*  mask  = d_in[1];
    const float* Wq    = (const float*)d_in[2];
    const float* bq    = (const float*)d_in[3];
    const float* Wk    = (const float*)d_in[4];
    const float* bk    = (const float*)d_in[5];
    const float* Wv    = (const float*)d_in[6];
    const float* bv    = (const float*)d_in[7];
    const float* Wo    = (const float*)d_in[8];
    const float* bo    = (const float*)d_in[9];
    const float* rel   = (const float*)d_in[10];
    const float* Wih_f = (const float*)d_in[11];
    const float* Whh_f = (const float*)d_in[12];
    const float* bih_f = (const float*)d_in[13];
    const float* bhh_f = (const float*)d_in[14];
    const float* Wih_b = (const float*)d_in[15];
    const float* Whh_b = (const float*)d_in[16];
    const float* bih_b = (const float*)d_in[17];
    const float* bhh_b = (const float*)d_in[18];

    float* out = (float*)d_out;
    const int attn_in_out = (out_size >= NOUT_ + BH_ * S_ * S_) ? 1 : 0;
    float* attn = attn_in_out ? (out + NOUT_) : nullptr;

    static int smem_set = 0;
    if (!smem_set) {
        cudaFuncSetAttribute(qkv_kernel,    cudaFuncAttributeMaxDynamicSharedMemorySize, SMEMB);
        cudaFuncSetAttribute(rnn_in_kernel, cudaFuncAttributeMaxDynamicSharedMemorySize, SMEMB);
        cudaFuncSetAttribute(rnn_h2f_kernel,cudaFuncAttributeMaxDynamicSharedMemorySize, SMEMB);
        cudaFuncSetAttribute(rnn_h2b_kernel,cudaFuncAttributeMaxDynamicSharedMemorySize, SMEMB);
        cudaFuncSetAttribute(scores_kernel, cudaFuncAttributeMaxDynamicSharedMemorySize, SMEMB);
        cudaFuncSetAttribute(ctx_kernel,    cudaFuncAttributeMaxDynamicSharedMemorySize, SMEMB);
        cudaFuncSetAttribute(out_kernel,    cudaFuncAttributeMaxDynamicSharedMemorySize, SMEMB);
        smem_set = 1;
    }

    mask_norm_kernel<<<1, 1024>>>(mask);

    qkv_kernel<<<dim3(D_ / 128, MS_ / 256, 3), 256, SMEMB>>>(x, Wq, bq, Wk, bk, Wv, bv);

    rnn_in_kernel<<<dim3(1, NR_ / 256, 2), 256, SMEMB>>>(Wih_f, bih_f, Wih_b, bih_b);
    rnn_h1_kernel<<<(NR_ * DP_) / 256, 256>>>(bih_f, bhh_f, bhh_b);
    rnn_h2f_kernel<<<dim3(1, NR_ / 256), 256, SMEMB>>>(Whh_f, bhh_f);
    rnn_h2b_kernel<<<dim3(1, NR_ / 256), 256, SMEMB>>>(Whh_b, bih_b, bhh_b);

    p_kernel<<<(ROWS_ * 65 + 255) / 256, 256>>>(rel);

    scores_kernel<<<dim3(S_ / 128, S_ / 256, BH_), 256, SMEMB>>>(attn, attn_in_out);
    softmax_kernel<<<ROWS_, 256>>>(attn, attn_in_out);
    ctx_kernel<<<dim3(1, S_ / 256, BH_), 256, SMEMB>>>(attn, attn_in_out);
    ctx_rel_kernel<<<(ROWS_ * DP_) / 256, 256>>>(rel);
    out_kernel<<<dim3(D_ / 128, MS_ / 256), 256, SMEMB>>>(Wo, bo, out);
}

// round 7
// speedup vs baseline: 1.1345x; 1.1345x over previous
#include <cuda_runtime.h>
#include <math.h>

// ---------------------------------------------------------------------------
// Problem constants
// ---------------------------------------------------------------------------
namespace {
constexpr int B_   = 8;
constexpr int S_   = 512;
constexpr int D_   = 1024;
constexpr int H_   = 8;
constexpr int DP_  = 128;              // head dim
constexpr int BH_  = B_ * H_;          // 64
constexpr int MS_  = B_ * S_;          // 4096  (rows of x)
constexpr int NR_  = 96 * S_;          // 49152 RNN rows
constexpr int ROWS_ = BH_ * S_;        // 32768 (b,h,q) rows
constexpr int NOUT_ = MS_ * D_;        // 4194304 elements of `out`
constexpr float INV_SCALE = 0.08838834764831845f;  // 1/sqrt(128)
// smem: A[3][128][20] + B_tn[3][128][20]  /  B_nn[3][16][136]
constexpr int SMEM_TN = (3 * 128 * 20 + 3 * 128 * 20) * 4;   // 61440
constexpr int SMEM_NN = (3 * 128 * 20 + 3 * 16 * 136) * 4;   // 56832
}

// ---------------------------------------------------------------------------
// Scratch (static device globals -- no runtime allocation allowed)
// ---------------------------------------------------------------------------
__device__ float g_q  [BH_ * S_ * DP_];
__device__ float g_k  [BH_ * S_ * DP_];
__device__ float g_v  [BH_ * S_ * DP_];
__device__ float g_ctx[BH_ * S_ * DP_];
__device__ float g_A  [NR_ * DP_];
__device__ float g_Bm [NR_ * DP_];
__device__ float g_H1f[NR_ * DP_];
__device__ float g_H1b[NR_ * DP_];
__device__ float g_Yf [NR_ * DP_];
__device__ float g_P  [ROWS_ * 65];
__device__ float g_R  [ROWS_ * 65];
__device__ int   g_mask[MS_];
__device__ float g_attn_fb[(size_t)BH_ * S_ * S_];
// tf32-rounded operand copies
__device__ float g_xr  [MS_ * D_];
__device__ float g_Wqr [D_ * D_];
__device__ float g_Wkr [D_ * D_];
__device__ float g_Wvr [D_ * D_];
__device__ float g_Wor [D_ * D_];
__device__ float g_Wihfr[DP_ * DP_];
__device__ float g_Whhfr[DP_ * DP_];
__device__ float g_Wihbr[DP_ * DP_];
__device__ float g_Whhbr[DP_ * DP_];

// ---------------------------------------------------------------------------
// tf32 / cp.async helpers
// ---------------------------------------------------------------------------
__device__ __forceinline__ unsigned f2tf(float x) {
    unsigned r;
    asm("cvt.rna.tf32.f32 %0, %1;" : "=r"(r) : "f"(x));
    return r;
}
__device__ __forceinline__ float rtf(float x) { return __uint_as_float(f2tf(x)); }

__device__ __forceinline__ void mma_tf32(float* d, const unsigned* a, const unsigned* b) {
    asm volatile(
        "mma.sync.aligned.m16n8k8.row.col.f32.tf32.tf32.f32 "
        "{%0,%1,%2,%3}, {%4,%5,%6,%7}, {%8,%9}, {%0,%1,%2,%3};\n"
        : "+f"(d[0]), "+f"(d[1]), "+f"(d[2]), "+f"(d[3])
        : "r"(a[0]), "r"(a[1]), "r"(a[2]), "r"(a[3]), "r"(b[0]), "r"(b[1]));
}

__device__ __forceinline__ void cp16(void* s, const void* g) {
    unsigned a = (unsigned)__cvta_generic_to_shared(s);
    asm volatile("cp.async.cg.shared.global [%0], [%1], 16;" :: "r"(a), "l"(g));
}
__device__ __forceinline__ void cp_commit() { asm volatile("cp.async.commit_group;"); }
__device__ __forceinline__ void cp_wait1()  { asm volatile("cp.async.wait_group 1;"); }

// ---------------------------------------------------------------------------
// 128x128 tf32 MMA cores with cp.async 3-stage pipeline.
// 256 threads = 8 warps (2M x 4N), warp tile 64x32.
// Operands must already be tf32-rounded in gmem.
//   ca_tn: C = A * B^T  (rowA(r,k)/rowB(r,k) -> const float* at [row r, col k])
//   ca_nn: C = A * B    (rowB(k,n) -> const float* at [row k, col n])
// ---------------------------------------------------------------------------
template <class FA, class FB, class FC>
__device__ __forceinline__ void ca_tn(int K, FA rowA, FB rowB, FC storeC) {
    extern __shared__ unsigned sm_[];
    unsigned (*As)[128][20] = reinterpret_cast<unsigned(*)[128][20]>(sm_);
    unsigned (*Bs)[128][20] = reinterpret_cast<unsigned(*)[128][20]>(sm_ + 3 * 128 * 20);
    const int tid  = threadIdx.x;
    const int lane = tid & 31, warp = tid >> 5;
    const int la3  = lane & 3, lg = lane >> 2;
    const int wm   = (warp & 1) * 64, wn = (warp >> 1) * 32;
    const int lr   = tid >> 2, lc = (tid & 3) * 4;
    float acc[4][4][4] = {};
    const int nk = K / 16;
    auto issue = [&](int st, int k0) {
        cp16(&As[st][lr][lc],      rowA(lr,      k0 + lc));
        cp16(&As[st][lr + 64][lc], rowA(lr + 64, k0 + lc));
        cp16(&Bs[st][lr][lc],      rowB(lr,      k0 + lc));
        cp16(&Bs[st][lr + 64][lc], rowB(lr + 64, k0 + lc));
    };
    issue(0, 0);  cp_commit();
    issue(1, 16); cp_commit();
    int st = 0;
    for (int it = 0; it < nk; it++) {
        cp_wait1();
        __syncthreads();
        if (it + 2 < nk) {
            int ns = st + 2; if (ns >= 3) ns -= 3;
            issue(ns, (it + 2) * 16);
        }
        cp_commit();
#pragma unroll
        for (int kc = 0; kc < 16; kc += 8) {
            unsigned af[4][4], bf[4][2];
#pragma unroll
            for (int mi = 0; mi < 4; mi++) {
                int m0 = wm + 16 * mi;
                af[mi][0] = As[st][m0 + lg][kc + la3];
                af[mi][1] = As[st][m0 + 8 + lg][kc + la3];
                af[mi][2] = As[st][m0 + lg][kc + 4 + la3];
                af[mi][3] = As[st][m0 + 8 + lg][kc + 4 + la3];
            }
#pragma unroll
            for (int nj = 0; nj < 4; nj++) {
                int n0 = wn + 8 * nj;
                bf[nj][0] = Bs[st][n0 + lg][kc + la3];
                bf[nj][1] = Bs[st][n0 + lg][kc + 4 + la3];
            }
#pragma unroll
            for (int mi = 0; mi < 4; mi++)
#pragma unroll
                for (int nj = 0; nj < 4; nj++) mma_tf32(acc[mi][nj], af[mi], bf[nj]);
        }
        if (++st == 3) st = 0;
    }
#pragma unroll
    for (int mi = 0; mi < 4; mi++)
#pragma unroll
        for (int nj = 0; nj < 4; nj++) {
            int r = wm + 16 * mi + lg, c = wn + 8 * nj + 2 * la3;
            storeC(r,     c,     acc[mi][nj][0]);
            storeC(r,     c + 1, acc[mi][nj][1]);
            storeC(r + 8, c,     acc[mi][nj][2]);
            storeC(r + 8, c + 1, acc[mi][nj][3]);
        }
}

template <class FA, class FB, class FC>
__device__ __forceinline__ void ca_nn(int K, FA rowA, FB rowB, FC storeC) {
    extern __shared__ unsigned sm_[];
    unsigned (*As)[128][20] = reinterpret_cast<unsigned(*)[128][20]>(sm_);
    unsigned (*Bs)[16][136] = reinterpret_cast<unsigned(*)[16][136]>(sm_ + 3 * 128 * 20);
    const int tid  = threadIdx.x;
    const int lane = tid & 31, warp = tid >> 5;
    const int la3  = lane & 3, lg = lane >> 2;
    const int wm   = (warp & 1) * 64, wn = (warp >> 1) * 32;
    const int lr   = tid >> 2, lc = (tid & 3) * 4;
    const int br   = tid >> 5, bc = (tid & 31) * 4;
    float acc[4][4][4] = {};
    const int nk = K / 16;
    auto issue = [&](int st, int k0) {
        cp16(&As[st][lr][lc],      rowA(lr,      k0 + lc));
        cp16(&As[st][lr + 64][lc], rowA(lr + 64, k0 + lc));
        cp16(&Bs[st][br][bc],      rowB(k0 + br,     bc));
        cp16(&Bs[st][br + 8][bc],  rowB(k0 + br + 8, bc));
    };
    issue(0, 0);  cp_commit();
    issue(1, 16); cp_commit();
    int st = 0;
    for (int it = 0; it < nk; it++) {
        cp_wait1();
        __syncthreads();
        if (it + 2 < nk) {
            int ns = st + 2; if (ns >= 3) ns -= 3;
            issue(ns, (it + 2) * 16);
        }
        cp_commit();
#pragma unroll
        for (int kc = 0; kc < 16; kc += 8) {
            unsigned af[4][4], bf[4][2];
#pragma unroll
            for (int mi = 0; mi < 4; mi++) {
                int m0 = wm + 16 * mi;
                af[mi][0] = As[st][m0 + lg][kc + la3];
                af[mi][1] = As[st][m0 + 8 + lg][kc + la3];
                af[mi][2] = As[st][m0 + lg][kc + 4 + la3];
                af[mi][3] = As[st][m0 + 8 + lg][kc + 4 + la3];
            }
#pragma unroll
            for (int nj = 0; nj < 4; nj++) {
                int n0 = wn + 8 * nj;
                bf[nj][0] = Bs[st][kc + la3][n0 + lg];
                bf[nj][1] = Bs[st][kc + 4 + la3][n0 + lg];
            }
#pragma unroll
            for (int mi = 0; mi < 4; mi++)
#pragma unroll
                for (int nj = 0; nj < 4; nj++) mma_tf32(acc[mi][nj], af[mi], bf[nj]);
        }
        if (++st == 3) st = 0;
    }
#pragma unroll
    for (int mi = 0; mi < 4; mi++)
#pragma unroll
        for (int nj = 0; nj < 4; nj++) {
            int r = wm + 16 * mi + lg, c = wn + 8 * nj + 2 * la3;
            storeC(r,     c,     acc[mi][nj][0]);
            storeC(r,     c + 1, acc[mi][nj][1]);
            storeC(r + 8, c,     acc[mi][nj][2]);
            storeC(r + 8, c + 1, acc[mi][nj][3]);
        }
}

// ---------------------------------------------------------------------------
// tf32 pre-rounding of GEMM operands (rna, once)
// ---------------------------------------------------------------------------
__global__ void round_kernel(const float4* __restrict__ src, float4* __restrict__ dst, int n4) {
    int i = blockIdx.x * blockDim.x + threadIdx.x;
    if (i >= n4) return;
    float4 v = src[i];
    v.x = rtf(v.x); v.y = rtf(v.y); v.z = rtf(v.z); v.w = rtf(v.w);
    dst[i] = v;
}

// ---------------------------------------------------------------------------
// 0) Mask normalization (detect uint8 / int32 / float32 encodings)
// ---------------------------------------------------------------------------
__global__ void mask_norm_kernel(const void* raw) {
    __shared__ int f_int, f_flt;
    const unsigned int* w = (const unsigned int*)raw;
    int t = threadIdx.x;  // 1024 threads
    if (t == 0) { f_int = 1; f_flt = 1; }
    __syncthreads();
    unsigned int x = w[t];
    if (x != 0u && x != 1u) f_int = 0;
    if (x != 0u && x != 0x3F800000u) f_flt = 0;
    __syncthreads();
    if (f_int) {
        for (int i = t; i < MS_; i += 1024) g_mask[i] = (int)w[i];
    } else if (f_flt) {
        const float* f = (const float*)raw;
        for (int i = t; i < MS_; i += 1024) g_mask[i] = (f[i] != 0.f);
    } else {
        const unsigned char* bts = (const unsigned char*)raw;
        for (int i = t; i < MS_; i += 1024) g_mask[i] = (bts[i] != 0);
    }
}

// ---------------------------------------------------------------------------
// 1) QKV projections + bias + mask-zero + head-major scatter (rounded out)
// ---------------------------------------------------------------------------
__global__ void __launch_bounds__(256) qkv_kernel(
    const float* __restrict__ bq, const float* __restrict__ bk,
    const float* __restrict__ bv) {
    const int z = blockIdx.z;
    const float* W    = (z == 0) ? g_Wqr : (z == 1) ? g_Wkr : g_Wvr;
    const float* bias = (z == 0) ? bq : (z == 1) ? bk : bv;
    float* out        = (z == 0) ? g_q : (z == 1) ? g_k : g_v;
    const int bm = blockIdx.y * 128, bn = blockIdx.x * 128;
    ca_tn(D_,
        [&](int r, int k) { return g_xr + (size_t)(bm + r) * D_ + k; },
        [&](int r, int k) { return W + (size_t)(bn + r) * D_ + k; },
        [&](int il, int jl, float v) {
            int m = bm + il, n = bn + jl;
            int b = m >> 9, s = m & 511;
            int h = n >> 7, d = n & 127;
            float val = g_mask[m] ? 0.f : rtf(v + bias[n]);
            out[((size_t)((b * H_ + h) * S_ + s)) * DP_ + d] = val;
        });
}

// ---------------------------------------------------------------------------
// 2) RNN input GEMMs
// ---------------------------------------------------------------------------
__device__ __forceinline__ const float* feats_row(int rr) {
    int f = rr >> 14;
    int rem = rr & 16383;
    int bh4 = rem >> 9;
    int s   = rem & 511;
    int b = bh4 >> 2, hh = bh4 & 3;
    const float* src = (f == 0) ? g_q : (f == 1) ? g_k : g_v;
    return src + ((size_t)((b * H_ + 4 + hh) * S_ + s)) * DP_;
}

__global__ void __launch_bounds__(256) rnn_in_kernel(
    const float* __restrict__ bih_f, const float* __restrict__ bih_b) {
    const int z = blockIdx.z;
    const float* W    = z ? g_Wihbr : g_Wihfr;
    const float* bias = z ? bih_b : bih_f;
    float* dst        = z ? g_Bm : g_A;
    const int bm = blockIdx.y * 128;
    ca_tn(DP_,
        [&](int r, int k) { return feats_row(bm + r) + k; },
        [&](int r, int k) { return W + (size_t)r * DP_ + k; },
        [&](int il, int jl, float v) {
            dst[(size_t)(bm + il) * DP_ + jl] = v + bias[jl];
        });
}

// ---------------------------------------------------------------------------
// 3) First RNN step (elementwise; rounded out -- H1 feeds GEMMs)
// ---------------------------------------------------------------------------
__global__ void rnn_h1_kernel(const float* __restrict__ bih_f,
                              const float* __restrict__ bhh_f,
                              const float* __restrict__ bhh_b) {
    int gid = blockIdx.x * blockDim.x + threadIdx.x;
    if (gid >= NR_ * DP_) return;
    int r = gid >> 7, d = gid & 127;
    int s = r & 511;
    float af = s ? g_A[gid - DP_] : bih_f[d];
    g_H1f[gid] = rtf(tanhf(af + bhh_f[d]));
    g_H1b[gid] = rtf(tanhf(g_Bm[gid] + bhh_b[d]));
}

// ---------------------------------------------------------------------------
// 4) Forward step 2:  Yf = tanh( A + H1f@Whh_f^T + bhh_f )
// ---------------------------------------------------------------------------
__global__ void __launch_bounds__(256) rnn_h2f_kernel(const float* __restrict__ bhh_f) {
    const int bm = blockIdx.y * 128;
    ca_tn(DP_,
        [&](int r, int k) { return g_H1f + (size_t)(bm + r) * DP_ + k; },
        [&](int r, int k) { return g_Whhfr + (size_t)r * DP_ + k; },
        [&](int il, int jl, float v) {
            size_t idx = (size_t)(bm + il) * DP_ + jl;
            g_Yf[idx] = tanhf(v + g_A[idx] + bhh_f[jl]);
        });
}

// ---------------------------------------------------------------------------
// 5) Backward step 2 + combine + scatter back into q/k/v heads 4..7 (rounded)
// ---------------------------------------------------------------------------
__global__ void __launch_bounds__(256) rnn_h2b_kernel(
    const float* __restrict__ bih_b, const float* __restrict__ bhh_b) {
    const int bm = blockIdx.y * 128;
    ca_tn(DP_,
        [&](int r, int k) { return g_H1b + (size_t)(bm + r) * DP_ + k; },
        [&](int r, int k) { return g_Whhbr + (size_t)r * DP_ + k; },
        [&](int il, int jl, float v) {
            int m = bm + il, n = jl;
            int s = m & 511;
            float shiftB = s ? g_Bm[(size_t)(m - 1) * DP_ + n] : bih_b[n];
            float y = g_Yf[(size_t)m * DP_ + n] + tanhf(v + shiftB + bhh_b[n]);
            int f = m >> 14, rem = m & 16383, bh4 = rem >> 9;
            int b = bh4 >> 2, hh = bh4 & 3;
            float* dst = (f == 0) ? g_q : (f == 1) ? g_k : g_v;
            dst[((size_t)((b * H_ + 4 + hh) * S_ + s)) * DP_ + n] = rtf(y);
        });
}

// ---------------------------------------------------------------------------
// 6) P[row,j] = (q[row] . rel_emb[j]) / SCALE
// ---------------------------------------------------------------------------
__global__ void p_kernel(const float* __restrict__ rel_emb) {
    int gid = blockIdx.x * blockDim.x + threadIdx.x;
    if (gid >= ROWS_ * 65) return;
    int row = gid / 65, j = gid - row * 65;
    const float* qr = g_q + (size_t)row * DP_;
    const float* er = rel_emb + (size_t)j * DP_;
    float s = 0.f;
#pragma unroll 8
    for (int d = 0; d < DP_; d++) s = fmaf(qr[d], er[d], s);
    g_P[gid] = s * INV_SCALE;
}

// ---------------------------------------------------------------------------
// 7) scores (pre-softmax) into the attn buffer
// ---------------------------------------------------------------------------
__global__ void __launch_bounds__(256) scores_kernel(float* __restrict__ attn,
                                                     int attn_in_out) {
    float* ap = attn_in_out ? attn : g_attn_fb;
    const int z = blockIdx.z;
    const int b = z >> 3;
    const int bm = blockIdx.y * 128, bn = blockIdx.x * 128;
    const float* qb = g_q + (size_t)z * S_ * DP_;
    const float* kb = g_k + (size_t)z * S_ * DP_;
    ca_tn(DP_,
        [&](int r, int k) { return qb + (size_t)(bm + r) * DP_ + k; },
        [&](int r, int k) { return kb + (size_t)(bn + r) * DP_ + k; },
        [&](int il, int jl, float v) {
            int qi = bm + il, ki = bn + jl;
            float val;
            if (g_mask[b * S_ + ki]) {
                val = -1e18f;
            } else {
                int off = ki - qi;
                off = off < -32 ? -32 : (off > 32 ? 32 : off);
                val = v * INV_SCALE + g_P[((size_t)z * S_ + qi) * 65 + off + 32];
            }
            ap[(size_t)z * S_ * S_ + (size_t)qi * S_ + ki] = val;
        });
}

// ---------------------------------------------------------------------------
// 8) Softmax per row + bucketed rel sums R
// ---------------------------------------------------------------------------
__device__ __forceinline__ float blk_reduce(float v, float* red, bool is_max) {
#pragma unroll
    for (int o = 16; o > 0; o >>= 1) {
        float w = __shfl_xor_sync(0xffffffffu, v, o);
        v = is_max ? fmaxf(v, w) : (v + w);
    }
    int warp = threadIdx.x >> 5, lane = threadIdx.x & 31;
    if (lane == 0) red[warp] = v;
    __syncthreads();
    float r = red[0];
#pragma unroll
    for (int i = 1; i < 8; i++) r = is_max ? fmaxf(r, red[i]) : (r + red[i]);
    __syncthreads();
    return r;
}

__global__ void __launch_bounds__(256) softmax_kernel(float* __restrict__ attn,
                                                      int attn_in_out) {
    float* ap = attn_in_out ? attn : g_attn_fb;
    int row = blockIdx.x;
    int q = row & 511;
    float* p = ap + (size_t)row * S_;
    __shared__ float sh[S_];
    __shared__ float red[8];
    int t = threadIdx.x;
    float v0 = p[t], v1 = p[t + 256];
    float mx = blk_reduce(fmaxf(v0, v1), red, true);
    float e0 = expf(v0 - mx), e1 = expf(v1 - mx);
    float sum = blk_reduce(e0 + e1, red, false);
    float inv = 1.f / sum;
    e0 *= inv; e1 *= inv;
    p[t] = e0; p[t + 256] = e1;
    sh[t] = e0; sh[t + 256] = e1;
    float r0 = 0.f, r64 = 0.f;
    if (t <= q - 32)        r0  += e0;
    if (t >= q + 32)        r64 += e0;
    if (t + 256 <= q - 32)  r0  += e1;
    if (t + 256 >= q + 32)  r64 += e1;
    r0  = blk_reduce(r0,  red, false);
    r64 = blk_reduce(r64, red, false);
    float* Rr = g_R + (size_t)row * 65;
    if (t == 0) { Rr[0] = r0; Rr[64] = r64; }
    if (t >= 1 && t <= 63) {
        int k = q + t - 32;
        Rr[t] = (k >= 0 && k < S_) ? sh[k] : 0.f;
    }
}

// ---------------------------------------------------------------------------
// 9) ctx = attn @ v  (NN, per bh; attn enters truncated -- acceptable)
// ---------------------------------------------------------------------------
__global__ void __launch_bounds__(256) ctx_kernel(const float* __restrict__ attn,
                                                  int attn_in_out) {
    const float* ap = attn_in_out ? attn : g_attn_fb;
    const int z = blockIdx.z;
    const int bm = blockIdx.y * 128;
    const float* Ab = ap + (size_t)z * S_ * S_;
    const float* Vb = g_v + (size_t)z * S_ * DP_;
    ca_nn(S_,
        [&](int r, int k) { return Ab + (size_t)(bm + r) * S_ + k; },
        [&](int k, int n) { return Vb + (size_t)k * DP_ + n; },
        [&](int il, int jl, float v) {
            g_ctx[(size_t)z * S_ * DP_ + (size_t)(bm + il) * DP_ + jl] = v;
        });
}

// ---------------------------------------------------------------------------
// 10) ctx += R @ rel_emb  (rounded out -- feeds out GEMM)
// ---------------------------------------------------------------------------
__global__ void ctx_rel_kernel(const float* __restrict__ rel_emb) {
    int gid = blockIdx.x * blockDim.x + threadIdx.x;
    if (gid >= ROWS_ * DP_) return;
    int row = gid >> 7, d = gid & 127;
    const float* Rr = g_R + (size_t)row * 65;
    float s = 0.f;
#pragma unroll
    for (int j = 0; j < 65; j++) s = fmaf(Rr[j], rel_emb[(size_t)j * DP_ + d], s);
    g_ctx[gid] = rtf(g_ctx[gid] + s);
}

// ---------------------------------------------------------------------------
// 11) out = ctx_perm @ Wo^T + bo
// ---------------------------------------------------------------------------
__global__ void __launch_bounds__(256) out_kernel(const float* __restrict__ bo,
                                                  float* __restrict__ out) {
    const int bm = blockIdx.y * 128, bn = blockIdx.x * 128;
    ca_tn(D_,
        [&](int r, int k) {
            int m = bm + r;
            int b = m >> 9, s = m & 511;
            int h = k >> 7, d = k & 127;
            return g_ctx + ((size_t)((b * H_ + h) * S_ + s)) * DP_ + d;
        },
        [&](int r, int k) { return g_Wor + (size_t)(bn + r) * D_ + k; },
        [&](int il, int jl, float v) {
            int m = bm + il, n = bn + jl;
            out[(size_t)m * D_ + n] = v + bo[n];
        });
}

// ---------------------------------------------------------------------------
// Host launcher
// ---------------------------------------------------------------------------
extern "C" void kernel_launch(void* const* d_in, const int* in_sizes, int n_in,
                              void* d_out, int out_size) {
    const float* x     = (const float*)d_in[0];
    const void*  mask  = d_in[1];
    const float* Wq    = (const float*)d_in[2];
    const float* bq    = (const float*)d_in[3];
    const float* Wk    = (const float*)d_in[4];
    const float* bk    = (const float*)d_in[5];
    const float* Wv    = (const float*)d_in[6];
    const float* bv    = (const float*)d_in[7];
    const float* Wo    = (const float*)d_in[8];
    const float* bo    = (const float*)d_in[9];
    const float* rel   = (const float*)d_in[10];
    const float* Wih_f = (const float*)d_in[11];
    const float* Whh_f = (const float*)d_in[12];
    const float* bih_f = (const float*)d_in[13];
    const float* bhh_f = (const float*)d_in[14];
    const float* Wih_b = (const float*)d_in[15];
    const float* Whh_b = (const float*)d_in[16];
    const float* bih_b = (const float*)d_in[17];
    const float* bhh_b = (const float*)d_in[18];

    float* out = (float*)d_out;
    const int attn_in_out = (out_size >= NOUT_ + BH_ * S_ * S_) ? 1 : 0;
    float* attn = attn_in_out ? (out + NOUT_) : nullptr;

    static int smem_set = 0;
    if (!smem_set) {
        cudaFuncSetAttribute(qkv_kernel,     cudaFuncAttributeMaxDynamicSharedMemorySize, SMEM_TN);
        cudaFuncSetAttribute(rnn_in_kernel,  cudaFuncAttributeMaxDynamicSharedMemorySize, SMEM_TN);
        cudaFuncSetAttribute(rnn_h2f_kernel, cudaFuncAttributeMaxDynamicSharedMemorySize, SMEM_TN);
        cudaFuncSetAttribute(rnn_h2b_kernel, cudaFuncAttributeMaxDynamicSharedMemorySize, SMEM_TN);
        cudaFuncSetAttribute(scores_kernel,  cudaFuncAttributeMaxDynamicSharedMemorySize, SMEM_TN);
        cudaFuncSetAttribute(ctx_kernel,     cudaFuncAttributeMaxDynamicSharedMemorySize, SMEM_NN);
        cudaFuncSetAttribute(out_kernel,     cudaFuncAttributeMaxDynamicSharedMemorySize, SMEM_TN);
        smem_set = 1;
    }

    // tf32 pre-rounding (rna) of all GEMM operand tensors
    auto rnd = [&](const float* src, float* dst, int n) {
        round_kernel<<<(n / 4 + 255) / 256, 256>>>((const float4*)src, (float4*)dst, n / 4);
    };
    float* p_xr;  cudaGetSymbolAddress((void**)&p_xr,  g_xr);
    float* p_wq;  cudaGetSymbolAddress((void**)&p_wq,  g_Wqr);
    float* p_wk;  cudaGetSymbolAddress((void**)&p_wk,  g_Wkr);
    float* p_wv;  cudaGetSymbolAddress((void**)&p_wv,  g_Wvr);
    float* p_wo;  cudaGetSymbolAddress((void**)&p_wo,  g_Wor);
    float* p_wif; cudaGetSymbolAddress((void**)&p_wif, g_Wihfr);
    float* p_whf; cudaGetSymbolAddress((void**)&p_whf, g_Whhfr);
    float* p_wib; cudaGetSymbolAddress((void**)&p_wib, g_Wihbr);
    float* p_whb; cudaGetSymbolAddress((void**)&p_whb, g_Whhbr);
    rnd(x, p_xr, MS_ * D_);
    rnd(Wq, p_wq, D_ * D_);
    rnd(Wk, p_wk, D_ * D_);
    rnd(Wv, p_wv, D_ * D_);
    rnd(Wo, p_wo, D_ * D_);
    rnd(Wih_f, p_wif, DP_ * DP_);
    rnd(Whh_f, p_whf, DP_ * DP_);
    rnd(Wih_b, p_wib, DP_ * DP_);
    rnd(Whh_b, p_whb, DP_ * DP_);

    mask_norm_kernel<<<1, 1024>>>(mask);

    qkv_kernel<<<dim3(D_ / 128, MS_ / 128, 3), 256, SMEM_TN>>>(bq, bk, bv);

    rnn_in_kernel<<<dim3(1, NR_ / 128, 2), 256, SMEM_TN>>>(bih_f, bih_b);
    rnn_h1_kernel<<<(NR_ * DP_) / 256, 256>>>(bih_f, bhh_f, bhh_b);
    rnn_h2f_kernel<<<dim3(1, NR_ / 128), 256, SMEM_TN>>>(bhh_f);
    rnn_h2b_kernel<<<dim3(1, NR_ / 128), 256, SMEM_TN>>>(bih_b, bhh_b);

    p_kernel<<<(ROWS_ * 65 + 255) / 256, 256>>>(rel);

    scores_kernel<<<dim3(S_ / 128, S_ / 128, BH_), 256, SMEM_TN>>>(attn, attn_in_out);
    softmax_kernel<<<ROWS_, 256>>>(attn, attn_in_out);
    ctx_kernel<<<dim3(1, S_ / 128, BH_), 256, SMEM_NN>>>(attn, attn_in_out);
    ctx_rel_kernel<<<(ROWS_ * DP_) / 256, 256>>>(rel);
    out_kernel<<<dim3(D_ / 128, MS_ / 128), 256, SMEM_TN>>>(bo, out);
}